// round 10
// baseline (speedup 1.0000x reference)
#include <cuda_runtime.h>
#include <cuda_bf16.h>
#include <cstdint>

#define N_NODES 25000
#define E_EDGES 200000

// Scratch (__device__ globals — allocation-free rule)
__device__ __nv_bfloat16 g_A[(size_t)E_EDGES * 128];  // [e][128]: [h_hi | h_lo]
__device__ __nv_bfloat16 g_B[(size_t)1024 * 128];     // [n][128]: [W_hi | W_lo]

// ---------------------------------------------------------------------------
// PTX helpers
// ---------------------------------------------------------------------------
__device__ __forceinline__ void mma16816(float* d, const uint32_t* a, const uint32_t* b) {
    asm volatile(
        "mma.sync.aligned.m16n8k16.row.col.f32.bf16.bf16.f32 "
        "{%0,%1,%2,%3}, {%4,%5,%6,%7}, {%8,%9}, {%0,%1,%2,%3};"
        : "+f"(d[0]), "+f"(d[1]), "+f"(d[2]), "+f"(d[3])
        : "r"(a[0]), "r"(a[1]), "r"(a[2]), "r"(a[3]), "r"(b[0]), "r"(b[1]));
}
__device__ __forceinline__ void ldsm_x4(uint32_t* r, uint32_t addr) {
    asm volatile("ldmatrix.sync.aligned.m8n8.x4.shared.b16 {%0,%1,%2,%3}, [%4];"
                 : "=r"(r[0]), "=r"(r[1]), "=r"(r[2]), "=r"(r[3]) : "r"(addr));
}
__device__ __forceinline__ uint32_t smem_u32(const void* p) {
    uint32_t a;
    asm("{ .reg .u64 t; cvta.to.shared.u64 t, %1; cvt.u32.u64 %0, t; }" : "=r"(a) : "l"(p));
    return a;
}
__device__ __forceinline__ void cpa16(uint32_t dst, const void* src, int src_sz) {
    asm volatile("cp.async.cg.shared.global [%0], [%1], 16, %2;"
                 :: "r"(dst), "l"(src), "r"(src_sz) : "memory");
}
#define CPA_COMMIT() asm volatile("cp.async.commit_group;" ::: "memory")
#define CPA_WAIT0() asm volatile("cp.async.wait_group 0;" ::: "memory")

// ---------------------------------------------------------------------------
// K_prep: merged (self-connection | hidden->A' | W2->B') via blockIdx dispatch
// ---------------------------------------------------------------------------
#define NB_SC 6250
#define NB_H 782
#define NB_PB 512

__global__ void __launch_bounds__(256) k_prep(
    const float* __restrict__ x, const float* __restrict__ el,
    const float* __restrict__ W1, const float* __restrict__ W2,
    const float* __restrict__ L0, const float* __restrict__ L1,
    float* __restrict__ out) {
    __shared__ float sA[512];
    int b = blockIdx.x, t = threadIdx.x;
    if (b < NB_SC) {
        sA[t] = L0[t];
        sA[256 + t] = L1[t];
        __syncthreads();
        int idx = b * 256 + t;
        int n = idx >> 6, o = idx & 63;
        const float* xr = x + (size_t)n * 64;
        float acc = 0.f;
        if (o < 16) {
            int v = o;
#pragma unroll
            for (int u = 0; u < 16; u++) acc += xr[u] * sA[u * 16 + v];
        } else {
            int q = o - 16;
            int v = q / 3, k = q - v * 3;
#pragma unroll
            for (int u = 0; u < 16; u++) acc += xr[16 + u * 3 + k] * sA[256 + u * 16 + v];
        }
        out[idx] = acc * 0.25f;
    } else if (b < NB_SC + NB_H) {
        sA[t] = W1[t];
        sA[t + 256] = W1[t + 256];
        __syncthreads();
        int e = (b - NB_SC) * 256 + t;
        if (e >= E_EDGES) return;
        float L = el[e];
        float r[8];
#pragma unroll
        for (int i = 0; i < 8; i++) {
            float d = L - (5.0f / 7.0f) * (float)i;
            r[i] = __expf(-0.5f * d * d);
        }
        uint32_t hiP[32], loP[32];
#pragma unroll 4
        for (int c2 = 0; c2 < 32; c2++) {
            float z0 = 0.f, z1 = 0.f;
#pragma unroll
            for (int i = 0; i < 8; i++) {
                z0 += r[i] * sA[i * 64 + 2 * c2];
                z1 += r[i] * sA[i * 64 + 2 * c2 + 1];
            }
            z0 *= 0.35355339059327373f;
            z1 *= 0.35355339059327373f;
            float h0 = z0 / (1.f + __expf(-z0)) * 0.125f;  // silu * (1/8)
            float h1 = z1 / (1.f + __expf(-z1)) * 0.125f;
            __nv_bfloat16 b0 = __float2bfloat16(h0);
            __nv_bfloat16 b1 = __float2bfloat16(h1);
            __nv_bfloat16 l0 = __float2bfloat16(h0 - __bfloat162float(b0));
            __nv_bfloat16 l1 = __float2bfloat16(h1 - __bfloat162float(b1));
            hiP[c2] = ((uint32_t)__bfloat16_as_ushort(b1) << 16) | __bfloat16_as_ushort(b0);
            loP[c2] = ((uint32_t)__bfloat16_as_ushort(l1) << 16) | __bfloat16_as_ushort(l0);
        }
        uint4* row = (uint4*)(g_A + (size_t)e * 128);
        const uint4* hp = (const uint4*)hiP;
        const uint4* lp = (const uint4*)loP;
#pragma unroll
        for (int i = 0; i < 8; i++) row[i] = hp[i];
#pragma unroll
        for (int i = 0; i < 8; i++) row[8 + i] = lp[i];
    } else {
        int idx = (b - NB_SC - NB_H) * 256 + t;
        int n = idx >> 7, k = idx & 127;
        int c = k & 63;
        float v = W2[c * 1024 + n];
        __nv_bfloat16 hi = __float2bfloat16(v);
        __nv_bfloat16 o = (k >= 64) ? __float2bfloat16(v - __bfloat162float(hi)) : hi;
        g_B[(size_t)n * 128 + k] = o;
    }
}

// ---------------------------------------------------------------------------
// K_fused: 128-edge tile, 512 threads. GEMM + fragment-side contraction with
// ZERO persistent register partials — contributions flushed to smem atomic
// accumulators each half. Final pass reads accumulators -> global atomics.
// ---------------------------------------------------------------------------
#define SAB_PITCH 136  // bf16/row (ldmatrix conflict-free @272B stride)
#define SXP 68         // s_x pitch in floats
#define SM_A 0
#define SM_B0 34816
#define SM_B1 69632
#define SM_X 104448
#define SM_EA 139264
#define SM_DST 141312
#define SM_L0 141824
#define SM_L1 150528
#define SM_O0 159232
#define SM_PS2 167936
#define SM_C1 176640
#define SM_TOTAL 201728

__global__ void __launch_bounds__(512, 1)
k_fused(const float* __restrict__ x,
        const float* __restrict__ ea,
        const int* __restrict__ esrc,
        const int* __restrict__ edst,
        float* __restrict__ out) {
    extern __shared__ char smraw[];
    uint32_t sbase = smem_u32(smraw);
    float* s_x = (float*)(smraw + SM_X);
    float* s_ea = (float*)(smraw + SM_EA);
    int* s_dst = (int*)(smraw + SM_DST);
    float* s_l0 = (float*)(smraw + SM_L0);
    float* s_l1 = (float*)(smraw + SM_L1);
    float* s_o0 = (float*)(smraw + SM_O0);   // [128][17]
    float* s_p2 = (float*)(smraw + SM_PS2);  // [128][17]
    float* s_c1 = (float*)(smraw + SM_C1);   // [128][49]

    int tid = threadIdx.x;
    long e0 = (long)blockIdx.x * 128;
    int rows = (int)(E_EDGES - e0);
    if (rows > 128) rows = 128;

    // ---- zero the accumulators (visible after h0's barrier)
    for (int f = tid; f < 128 * 17 * 2 + 128 * 49; f += 512)
        ((float*)(smraw + SM_O0))[f] = 0.f;

    // ---- stage group 0: A tile, x gather, ea, dst, B(0)
    for (int f = tid; f < 128 * 16; f += 512) {
        int r = f >> 4, q = f & 15;
        int ok = (r < rows) ? 16 : 0;
        cpa16(sbase + SM_A + r * (SAB_PITCH * 2) + q * 16,
              (const char*)(g_A + (size_t)(e0 + (ok ? r : 0)) * 128) + q * 16, ok);
    }
    for (int f = tid; f < 128 * 16; f += 512) {
        int r = f >> 4, q = f & 15;
        int ok = (r < rows) ? 16 : 0;
        int sn = ok ? esrc[e0 + r] : 0;
        cpa16(sbase + SM_X + r * (SXP * 4) + q * 16,
              (const char*)(x + (size_t)sn * 64) + q * 16, ok);
    }
    if (tid < 128) {
        int ok = (tid < rows) ? 16 : 0;
        cpa16(sbase + SM_EA + tid * 16,
              (const char*)(ea + (size_t)(e0 + (ok ? tid : 0)) * 4), ok);
    }
    if (tid < 32) {
        int ok = (tid * 4 < rows) ? 16 : 0;
        cpa16(sbase + SM_DST + tid * 16,
              (const char*)(edst + e0 + (ok ? tid * 4 : 0)), ok);
    }
    for (int f = tid; f < 128 * 16; f += 512) {
        int r = f >> 4, q = f & 15;
        cpa16(sbase + SM_B0 + r * (SAB_PITCH * 2) + q * 16,
              (const char*)(g_B + (size_t)r * 128) + q * 16, 16);
    }
    CPA_COMMIT();

    // warp roles (16 warps, 4x4 grid of 32x32 tiles over 128x128)
    int wid = tid >> 5, lane = tid & 31;
    int wm = (wid >> 2) * 32;
    int wn = (wid & 3) * 32;
    int grp = lane >> 2, qd = lane & 3;

    // ldmatrix lane bases
    int selA = lane >> 3;
    int rA = wm + ((selA & 1) << 3) + (lane & 7);
    int cA = (selA >> 1) << 3;
    uint32_t aF = sbase + SM_A + (uint32_t)(rA * SAB_PITCH + cA) * 2;
    int rB4 = wn + ((lane >> 4) << 3) + (lane & 7);
    int cB4 = ((lane >> 3) & 1) << 3;
    uint32_t bOff = (uint32_t)(rB4 * SAB_PITCH + cB4) * 2;

    // fragment row coordinates
    int er[4];
#pragma unroll
    for (int r = 0; r < 4; r++) er[r] = wm + ((r >> 1) << 4) + ((r & 1) << 3) + grp;

#pragma unroll 1
    for (int h = 0; h < 8; h++) {
        int sec = h >> 1, nh = h & 1;
        int ub = nh * 8;
        uint32_t bufo = (h & 1) ? SM_B1 : SM_B0;

        CPA_WAIT0();
        __syncthreads();  // B(h) (+ group0 + acc-zero on h=0) ready

        if (h == 0) {
            // precompute l0 = xj0*sh0, l1 = (x1 . sh1)/sqrt(3)
            for (int f = tid; f < 2048; f += 512) {
                int e = f >> 4, u = f & 15;
                const float* xr = s_x + e * SXP;
                s_l0[e * 17 + u] = xr[u] * s_ea[e * 4 + 0];
                const float* x1 = xr + 16 + u * 3;
                s_l1[e * 17 + u] = 0.57735026918962576f *
                                   (x1[0] * s_ea[e * 4 + 1] + x1[1] * s_ea[e * 4 + 2] +
                                    x1[2] * s_ea[e * 4 + 3]);
            }
            __syncthreads();
        }

        // prefetch B(h+1) into the other buffer
        if (h < 7) {
            uint32_t dstb = ((h & 1) ? SM_B0 : SM_B1) + sbase;
            const __nv_bfloat16* srcb = g_B + (size_t)(h + 1) * 128 * 128;
            for (int f = tid; f < 128 * 16; f += 512) {
                int r = f >> 4, q = f & 15;
                cpa16(dstb + r * (SAB_PITCH * 2) + q * 16,
                      (const char*)(srcb + (size_t)r * 128) + q * 16, 16);
            }
            CPA_COMMIT();
        }

        // ---- 128x128x192 GEMM (3 dedup terms), all-x4 ldmatrix
        float acc[2][4][4];
#pragma unroll
        for (int mt = 0; mt < 2; mt++)
#pragma unroll
            for (int nt = 0; nt < 4; nt++)
#pragma unroll
                for (int j = 0; j < 4; j++) acc[mt][nt][j] = 0.f;

        uint32_t bF = sbase + bufo + bOff;
#pragma unroll
        for (int kt = 0; kt < 4; kt++) {
            int kc = kt * 16;
            uint32_t ah[2][4], al[2][4], bh[2][4], bl[2][4];
#pragma unroll
            for (int mt = 0; mt < 2; mt++) {
                ldsm_x4(ah[mt], aF + (uint32_t)(mt * 16 * SAB_PITCH + kc) * 2);
                ldsm_x4(al[mt], aF + (uint32_t)(mt * 16 * SAB_PITCH + kc + 64) * 2);
            }
#pragma unroll
            for (int p = 0; p < 2; p++) {
                ldsm_x4(bh[p], bF + (uint32_t)(p * 16 * SAB_PITCH + kc) * 2);
                ldsm_x4(bl[p], bF + (uint32_t)(p * 16 * SAB_PITCH + kc + 64) * 2);
            }
#pragma unroll
            for (int mt = 0; mt < 2; mt++)
#pragma unroll
                for (int nt = 0; nt < 4; nt++) {
                    const uint32_t* bhf = &bh[nt >> 1][(nt & 1) * 2];
                    const uint32_t* blf = &bl[nt >> 1][(nt & 1) * 2];
                    mma16816(acc[mt][nt], ah[mt], bhf);
                    mma16816(acc[mt][nt], ah[mt], blf);
                    mma16816(acc[mt][nt], al[mt], bhf);
                }
        }

        // ---- flush fragment contributions into smem atomic accumulators
        // row = mt*2+(j>>1); u = ub+(wn>>4)+(nt>>1); v = (nt&1)*8+qd*2+(j&1)
        int u0 = ub + (wn >> 4);
        if (sec <= 1) {
            const float* lt = (sec == 0) ? s_l0 : s_l1;
            float la[4][2];
#pragma unroll
            for (int r = 0; r < 4; r++) {
                la[r][0] = lt[er[r] * 17 + u0];
                la[r][1] = lt[er[r] * 17 + u0 + 1];
            }
#pragma unroll
            for (int mt = 0; mt < 2; mt++)
#pragma unroll
                for (int nt = 0; nt < 4; nt++)
#pragma unroll
                    for (int j = 0; j < 4; j++) {
                        int r = mt * 2 + (j >> 1);
                        atomicAdd(&s_o0[er[r] * 17 + (nt & 1) * 8 + qd * 2 + (j & 1)],
                                  la[r][nt >> 1] * acc[mt][nt][j]);
                    }
        } else if (sec == 2) {
            float la[4][2];
#pragma unroll
            for (int r = 0; r < 4; r++) {
                la[r][0] = s_x[er[r] * SXP + u0];
                la[r][1] = s_x[er[r] * SXP + u0 + 1];
            }
#pragma unroll
            for (int mt = 0; mt < 2; mt++)
#pragma unroll
                for (int nt = 0; nt < 4; nt++)
#pragma unroll
                    for (int j = 0; j < 4; j++) {
                        int r = mt * 2 + (j >> 1);
                        atomicAdd(&s_p2[er[r] * 17 + (nt & 1) * 8 + qd * 2 + (j & 1)],
                                  la[r][nt >> 1] * acc[mt][nt][j]);
                    }
        } else {
            float la3[4][2][3];
#pragma unroll
            for (int r = 0; r < 4; r++)
#pragma unroll
                for (int u = 0; u < 2; u++) {
                    const float* x1 = s_x + er[r] * SXP + 16 + (u0 + u) * 3;
                    la3[r][u][0] = x1[0]; la3[r][u][1] = x1[1]; la3[r][u][2] = x1[2];
                }
#pragma unroll
            for (int mt = 0; mt < 2; mt++)
#pragma unroll
                for (int nt = 0; nt < 4; nt++)
#pragma unroll
                    for (int j = 0; j < 4; j++) {
                        int r = mt * 2 + (j >> 1);
                        int v = (nt & 1) * 8 + qd * 2 + (j & 1);
                        float a = acc[mt][nt][j];
                        float* base = &s_c1[er[r] * 49 + v * 3];
                        atomicAdd(base + 0, la3[r][nt >> 1][0] * a);
                        atomicAdd(base + 1, la3[r][nt >> 1][1] * a);
                        atomicAdd(base + 2, la3[r][nt >> 1][2] * a);
                    }
        }
    }

    // ---- final pass: read accumulators, fold per-edge constants, scatter
    __syncthreads();
    const float ALPHA = 0.17677669529663689f;  // 1/sqrt(32)
#pragma unroll
    for (int p = 0; p < 4; p++) {
        int idx = tid + p * 512;
        int e = idx >> 4, v = idx & 15;
        if (e < rows) {
            float* o = out + (size_t)s_dst[e] * 64;
            float sh0 = s_ea[e * 4 + 0];
            atomicAdd(o + v, s_o0[e * 17 + v] * ALPHA);
            float p2 = s_p2[e * 17 + v];
            const float* c1 = &s_c1[e * 49 + v * 3];
#pragma unroll
            for (int k = 0; k < 3; k++)
                atomicAdd(o + 16 + v * 3 + k,
                          (p2 * s_ea[e * 4 + 1 + k] + c1[k] * sh0) * ALPHA);
        }
    }
}

// ---------------------------------------------------------------------------
extern "C" void kernel_launch(void* const* d_in, const int* in_sizes, int n_in,
                              void* d_out, int out_size) {
    const float* x    = (const float*)d_in[0];
    const float* ea   = (const float*)d_in[1];
    const float* el   = (const float*)d_in[2];
    const int*   esrc = (const int*)d_in[3];
    const int*   edst = (const int*)d_in[4];
    const float* W1   = (const float*)d_in[5];
    const float* W2   = (const float*)d_in[6];
    const float* L0   = (const float*)d_in[7];
    const float* L1   = (const float*)d_in[8];
    float* out = (float*)d_out;

    (void)in_sizes; (void)n_in; (void)out_size;

    cudaFuncSetAttribute(k_fused, cudaFuncAttributeMaxDynamicSharedMemorySize, SM_TOTAL);

    // 1) merged prep: self-connection | hidden->A' | W2->B'
    k_prep<<<NB_SC + NB_H + NB_PB, 256>>>(x, el, W1, W2, L0, L1, out);
    // 2) fused GEMM + smem-accumulator contraction + scatter
    k_fused<<<(E_EDGES + 127) / 128, 512, SM_TOTAL>>>(x, ea, esrc, edst, out);
}

// round 12
// speedup vs baseline: 3.0087x; 3.0087x over previous
#include <cuda_runtime.h>
#include <cuda_bf16.h>
#include <cstdint>

#define N_NODES 25000
#define E_EDGES 200000

// Scratch (__device__ globals — allocation-free rule)
__device__ __nv_bfloat16 g_A[(size_t)E_EDGES * 128];  // [e][128]: [h_hi | h_lo]
__device__ __nv_bfloat16 g_B[(size_t)1024 * 128];     // [n][128]: [W_hi | W_lo]

// ---------------------------------------------------------------------------
// PTX helpers
// ---------------------------------------------------------------------------
__device__ __forceinline__ void mma16816(float* d, const uint32_t* a, const uint32_t* b) {
    asm volatile(
        "mma.sync.aligned.m16n8k16.row.col.f32.bf16.bf16.f32 "
        "{%0,%1,%2,%3}, {%4,%5,%6,%7}, {%8,%9}, {%0,%1,%2,%3};"
        : "+f"(d[0]), "+f"(d[1]), "+f"(d[2]), "+f"(d[3])
        : "r"(a[0]), "r"(a[1]), "r"(a[2]), "r"(a[3]), "r"(b[0]), "r"(b[1]));
}
__device__ __forceinline__ void ldsm_x4(uint32_t* r, uint32_t addr) {
    asm volatile("ldmatrix.sync.aligned.m8n8.x4.shared.b16 {%0,%1,%2,%3}, [%4];"
                 : "=r"(r[0]), "=r"(r[1]), "=r"(r[2]), "=r"(r[3]) : "r"(addr));
}
__device__ __forceinline__ uint32_t smem_u32(const void* p) {
    uint32_t a;
    asm("{ .reg .u64 t; cvta.to.shared.u64 t, %1; cvt.u32.u64 %0, t; }" : "=r"(a) : "l"(p));
    return a;
}
__device__ __forceinline__ void cpa16(uint32_t dst, const void* src, int src_sz) {
    asm volatile("cp.async.cg.shared.global [%0], [%1], 16, %2;"
                 :: "r"(dst), "l"(src), "r"(src_sz) : "memory");
}
#define CPA_COMMIT() asm volatile("cp.async.commit_group;" ::: "memory")
#define CPA_WAIT0() asm volatile("cp.async.wait_group 0;" ::: "memory")

// ---------------------------------------------------------------------------
// K_prep: merged (self-connection | hidden->A' | W2->B') via blockIdx dispatch
// ---------------------------------------------------------------------------
#define NB_SC 6250
#define NB_H 782
#define NB_PB 512

__global__ void __launch_bounds__(256) k_prep(
    const float* __restrict__ x, const float* __restrict__ el,
    const float* __restrict__ W1, const float* __restrict__ W2,
    const float* __restrict__ L0, const float* __restrict__ L1,
    float* __restrict__ out) {
    __shared__ float sA[512];
    int b = blockIdx.x, t = threadIdx.x;
    if (b < NB_SC) {
        sA[t] = L0[t];
        sA[256 + t] = L1[t];
        __syncthreads();
        int idx = b * 256 + t;
        int n = idx >> 6, o = idx & 63;
        const float* xr = x + (size_t)n * 64;
        float acc = 0.f;
        if (o < 16) {
            int v = o;
#pragma unroll
            for (int u = 0; u < 16; u++) acc += xr[u] * sA[u * 16 + v];
        } else {
            int q = o - 16;
            int v = q / 3, k = q - v * 3;
#pragma unroll
            for (int u = 0; u < 16; u++) acc += xr[16 + u * 3 + k] * sA[256 + u * 16 + v];
        }
        out[idx] = acc * 0.25f;
    } else if (b < NB_SC + NB_H) {
        sA[t] = W1[t];
        sA[t + 256] = W1[t + 256];
        __syncthreads();
        int e = (b - NB_SC) * 256 + t;
        if (e >= E_EDGES) return;
        float L = el[e];
        float r[8];
#pragma unroll
        for (int i = 0; i < 8; i++) {
            float d = L - (5.0f / 7.0f) * (float)i;
            r[i] = __expf(-0.5f * d * d);
        }
        uint32_t hiP[32], loP[32];
#pragma unroll 4
        for (int c2 = 0; c2 < 32; c2++) {
            float z0 = 0.f, z1 = 0.f;
#pragma unroll
            for (int i = 0; i < 8; i++) {
                z0 += r[i] * sA[i * 64 + 2 * c2];
                z1 += r[i] * sA[i * 64 + 2 * c2 + 1];
            }
            z0 *= 0.35355339059327373f;
            z1 *= 0.35355339059327373f;
            float h0 = z0 / (1.f + __expf(-z0)) * 0.125f;  // silu * (1/8)
            float h1 = z1 / (1.f + __expf(-z1)) * 0.125f;
            __nv_bfloat16 b0 = __float2bfloat16(h0);
            __nv_bfloat16 b1 = __float2bfloat16(h1);
            __nv_bfloat16 l0 = __float2bfloat16(h0 - __bfloat162float(b0));
            __nv_bfloat16 l1 = __float2bfloat16(h1 - __bfloat162float(b1));
            hiP[c2] = ((uint32_t)__bfloat16_as_ushort(b1) << 16) | __bfloat16_as_ushort(b0);
            loP[c2] = ((uint32_t)__bfloat16_as_ushort(l1) << 16) | __bfloat16_as_ushort(l0);
        }
        uint4* row = (uint4*)(g_A + (size_t)e * 128);
        const uint4* hp = (const uint4*)hiP;
        const uint4* lp = (const uint4*)loP;
#pragma unroll
        for (int i = 0; i < 8; i++) row[i] = hp[i];
#pragma unroll
        for (int i = 0; i < 8; i++) row[8 + i] = lp[i];
    } else {
        int idx = (b - NB_SC - NB_H) * 256 + t;
        int n = idx >> 7, k = idx & 127;
        int c = k & 63;
        float v = W2[c * 1024 + n];
        __nv_bfloat16 hi = __float2bfloat16(v);
        __nv_bfloat16 o = (k >= 64) ? __float2bfloat16(v - __bfloat162float(hi)) : hi;
        g_B[(size_t)n * 128 + k] = o;
    }
}

// ---------------------------------------------------------------------------
// K_fused: 128-edge tile, 512 threads. Fragment-side contraction with
// SECTION-SCOPED register partials (3 sequential h-loops -> max 48 live).
// ---------------------------------------------------------------------------
#define SAB_PITCH 136  // bf16/row (ldmatrix conflict-free @272B stride)
#define SXP 68         // s_x pitch in floats
#define SM_A 0
#define SM_B0 34816
#define SM_B1 69632
#define SM_X 104448
#define SM_EA 139264
#define SM_DST 141312
#define SM_L0 141824
#define SM_L1 150528
#define SM_TOTAL 159232
// po0 flush buffer aliases SM_L0 (l0+l1 region, 64*68*4 = 17408 B, dead by h>3)
// c1 reduction buffer aliases SM_B0 (dead after h=7)

__global__ void __launch_bounds__(512, 1)
k_fused(const float* __restrict__ x,
        const float* __restrict__ ea,
        const int* __restrict__ esrc,
        const int* __restrict__ edst,
        float* __restrict__ out) {
    extern __shared__ char smraw[];
    uint32_t sbase = smem_u32(smraw);
    float* s_x = (float*)(smraw + SM_X);
    float* s_ea = (float*)(smraw + SM_EA);
    int* s_dst = (int*)(smraw + SM_DST);
    float* s_l0 = (float*)(smraw + SM_L0);
    float* s_l1 = (float*)(smraw + SM_L1);

    int tid = threadIdx.x;
    long e0 = (long)blockIdx.x * 128;
    int rows = (int)(E_EDGES - e0);
    if (rows > 128) rows = 128;

    // ---- stage group 0: A tile, x gather, ea, dst, B(0)
    for (int f = tid; f < 128 * 16; f += 512) {
        int r = f >> 4, q = f & 15;
        int ok = (r < rows) ? 16 : 0;
        cpa16(sbase + SM_A + r * (SAB_PITCH * 2) + q * 16,
              (const char*)(g_A + (size_t)(e0 + (ok ? r : 0)) * 128) + q * 16, ok);
    }
    for (int f = tid; f < 128 * 16; f += 512) {
        int r = f >> 4, q = f & 15;
        int ok = (r < rows) ? 16 : 0;
        int sn = ok ? esrc[e0 + r] : 0;
        cpa16(sbase + SM_X + r * (SXP * 4) + q * 16,
              (const char*)(x + (size_t)sn * 64) + q * 16, ok);
    }
    if (tid < 128) {
        int ok = (tid < rows) ? 16 : 0;
        cpa16(sbase + SM_EA + tid * 16,
              (const char*)(ea + (size_t)(e0 + (ok ? tid : 0)) * 4), ok);
    }
    if (tid < 32) {
        int ok = (tid * 4 < rows) ? 16 : 0;
        cpa16(sbase + SM_DST + tid * 16,
              (const char*)(edst + e0 + (ok ? tid * 4 : 0)), ok);
    }
    for (int f = tid; f < 128 * 16; f += 512) {
        int r = f >> 4, q = f & 15;
        cpa16(sbase + SM_B0 + r * (SAB_PITCH * 2) + q * 16,
              (const char*)(g_B + (size_t)r * 128) + q * 16, 16);
    }
    CPA_COMMIT();

    // warp roles (16 warps, 4x4 grid of 32x32 tiles over 128x128)
    int wid = tid >> 5, lane = tid & 31;
    int wm = (wid >> 2) * 32;
    int wn = (wid & 3) * 32;
    int wng = wid & 3;
    int grp = lane >> 2, qd = lane & 3;

    // ldmatrix lane bases
    int selA = lane >> 3;
    int rA = wm + ((selA & 1) << 3) + (lane & 7);
    int cA = (selA >> 1) << 3;
    uint32_t aF = sbase + SM_A + (uint32_t)(rA * SAB_PITCH + cA) * 2;
    int rB4 = wn + ((lane >> 4) << 3) + (lane & 7);
    int cB4 = ((lane >> 3) & 1) << 3;
    uint32_t bOff = (uint32_t)(rB4 * SAB_PITCH + cB4) * 2;

    // fragment row coordinates
    int er[4];
#pragma unroll
    for (int r = 0; r < 4; r++) er[r] = wm + ((r >> 1) << 4) + ((r & 1) << 3) + grp;

    const float ALPHA = 0.17677669529663689f;  // 1/sqrt(32)

    // shared GEMM body for one half
    auto gemm_half = [&](int h, float (&acc)[2][4][4]) {
        uint32_t bufo = (h & 1) ? SM_B1 : SM_B0;
        CPA_WAIT0();
        __syncthreads();  // B(h) (+ group0 on h=0) ready; prev phase done
        if (h == 0) {
            // precompute l0 = xj0*sh0, l1 = (x1 . sh1)/sqrt(3)
            for (int f = tid; f < 2048; f += 512) {
                int e = f >> 4, u = f & 15;
                const float* xr = s_x + e * SXP;
                s_l0[e * 17 + u] = xr[u] * s_ea[e * 4 + 0];
                const float* x1 = xr + 16 + u * 3;
                s_l1[e * 17 + u] = 0.57735026918962576f *
                                   (x1[0] * s_ea[e * 4 + 1] + x1[1] * s_ea[e * 4 + 2] +
                                    x1[2] * s_ea[e * 4 + 3]);
            }
            __syncthreads();
        }
        // prefetch B(h+1)
        if (h < 7) {
            uint32_t dstb = ((h & 1) ? SM_B0 : SM_B1) + sbase;
            const __nv_bfloat16* srcb = g_B + (size_t)(h + 1) * 128 * 128;
            for (int f = tid; f < 128 * 16; f += 512) {
                int r = f >> 4, q = f & 15;
                cpa16(dstb + r * (SAB_PITCH * 2) + q * 16,
                      (const char*)(srcb + (size_t)r * 128) + q * 16, 16);
            }
            CPA_COMMIT();
        }
#pragma unroll
        for (int mt = 0; mt < 2; mt++)
#pragma unroll
            for (int nt = 0; nt < 4; nt++)
#pragma unroll
                for (int j = 0; j < 4; j++) acc[mt][nt][j] = 0.f;
        uint32_t bF = sbase + bufo + bOff;
#pragma unroll
        for (int kt = 0; kt < 4; kt++) {
            int kc = kt * 16;
            uint32_t ah[2][4], al[2][4], bh[2][4], bl[2][4];
#pragma unroll
            for (int mt = 0; mt < 2; mt++) {
                ldsm_x4(ah[mt], aF + (uint32_t)(mt * 16 * SAB_PITCH + kc) * 2);
                ldsm_x4(al[mt], aF + (uint32_t)(mt * 16 * SAB_PITCH + kc + 64) * 2);
            }
#pragma unroll
            for (int p = 0; p < 2; p++) {
                ldsm_x4(bh[p], bF + (uint32_t)(p * 16 * SAB_PITCH + kc) * 2);
                ldsm_x4(bl[p], bF + (uint32_t)(p * 16 * SAB_PITCH + kc + 64) * 2);
            }
#pragma unroll
            for (int mt = 0; mt < 2; mt++)
#pragma unroll
                for (int nt = 0; nt < 4; nt++) {
                    const uint32_t* bhf = &bh[nt >> 1][(nt & 1) * 2];
                    const uint32_t* blf = &bl[nt >> 1][(nt & 1) * 2];
                    mma16816(acc[mt][nt], ah[mt], bhf);
                    mma16816(acc[mt][nt], ah[mt], blf);
                    mma16816(acc[mt][nt], al[mt], bhf);
                }
        }
    };

    // ================= sections 0,1 (h=0..3): po0 only =================
    {
        float po0[4][4] = {};
#pragma unroll 1
        for (int h = 0; h < 4; h++) {
            float acc[2][4][4];
            gemm_half(h, acc);
            int u0 = (h & 1) * 8 + (wn >> 4);
            const float* lt = (h < 2) ? s_l0 : s_l1;
            float la[4][2];
#pragma unroll
            for (int r = 0; r < 4; r++) {
                la[r][0] = lt[er[r] * 17 + u0];
                la[r][1] = lt[er[r] * 17 + u0 + 1];
            }
#pragma unroll
            for (int mt = 0; mt < 2; mt++)
#pragma unroll
                for (int nt = 0; nt < 4; nt++)
#pragma unroll
                    for (int j = 0; j < 4; j++)
                        po0[mt * 2 + (j >> 1)][(nt & 1) * 2 + (j & 1)] +=
                            la[mt * 2 + (j >> 1)][nt >> 1] * acc[mt][nt][j];
        }
        // flush po0 (reduce across 4 wn-groups) + scatter o0 outputs.
        // Buffer aliases l0/l1 region (dead now): [64][68] floats, 2 sub-passes.
        float* fb = (float*)(smraw + SM_L0);
#pragma unroll 1
        for (int sp = 0; sp < 2; sp++) {
            __syncthreads();
            if ((wm >> 6) == sp) {
#pragma unroll
                for (int r = 0; r < 4; r++)
#pragma unroll
                    for (int s = 0; s < 4; s++) {
                        int v = (s >> 1) * 8 + qd * 2 + (s & 1);
                        fb[(er[r] - sp * 64) * 68 + v * 4 + wng] = po0[r][s];
                    }
            }
            __syncthreads();
#pragma unroll
            for (int p = 0; p < 2; p++) {
                int idx = tid + p * 512;
                int e2 = idx >> 4, v = idx & 15;
                int e = sp * 64 + e2;
                float4 s4 = *(float4*)&fb[e2 * 68 + v * 4];
                if (e < rows)
                    atomicAdd(out + (size_t)s_dst[e] * 64 + v,
                              (s4.x + s4.y + s4.z + s4.w) * ALPHA);
            }
        }
    }

    // ================= section 2 (h=4,5): ps2 -> c1 seed =================
    float c1[3][4][4];
    {
        float ps2[4][4] = {};
#pragma unroll 1
        for (int h = 4; h < 6; h++) {
            float acc[2][4][4];
            gemm_half(h, acc);
            int u0 = (h & 1) * 8 + (wn >> 4);
            float la[4][2];
#pragma unroll
            for (int r = 0; r < 4; r++) {
                la[r][0] = s_x[er[r] * SXP + u0];
                la[r][1] = s_x[er[r] * SXP + u0 + 1];
            }
#pragma unroll
            for (int mt = 0; mt < 2; mt++)
#pragma unroll
                for (int nt = 0; nt < 4; nt++)
#pragma unroll
                    for (int j = 0; j < 4; j++)
                        ps2[mt * 2 + (j >> 1)][(nt & 1) * 2 + (j & 1)] +=
                            la[mt * 2 + (j >> 1)][nt >> 1] * acc[mt][nt][j];
        }
#pragma unroll
        for (int r = 0; r < 4; r++) {
            float h1 = s_ea[er[r] * 4 + 1];
            float h2 = s_ea[er[r] * 4 + 2];
            float h3 = s_ea[er[r] * 4 + 3];
#pragma unroll
            for (int s = 0; s < 4; s++) {
                c1[0][r][s] = ps2[r][s] * h1;
                c1[1][r][s] = ps2[r][s] * h2;
                c1[2][r][s] = ps2[r][s] * h3;
            }
        }
    }

    // ========== section 3 (h=6,7): accumulate into c1 (sh0 folded) ==========
#pragma unroll 1
    for (int h = 6; h < 8; h++) {
        float acc[2][4][4];
        gemm_half(h, acc);
        int u0 = (h & 1) * 8 + (wn >> 4);
        float la3[4][2][3];
#pragma unroll
        for (int r = 0; r < 4; r++) {
            float sh0 = s_ea[er[r] * 4 + 0];
#pragma unroll
            for (int u = 0; u < 2; u++) {
                const float* x1 = s_x + er[r] * SXP + 16 + (u0 + u) * 3;
                la3[r][u][0] = x1[0] * sh0;
                la3[r][u][1] = x1[1] * sh0;
                la3[r][u][2] = x1[2] * sh0;
            }
        }
#pragma unroll
        for (int mt = 0; mt < 2; mt++)
#pragma unroll
            for (int nt = 0; nt < 4; nt++)
#pragma unroll
                for (int j = 0; j < 4; j++) {
                    int r = mt * 2 + (j >> 1), vs = (nt & 1) * 2 + (j & 1);
                    float a = acc[mt][nt][j];
                    c1[0][r][vs] += la3[r][nt >> 1][0] * a;
                    c1[1][r][vs] += la3[r][nt >> 1][1] * a;
                    c1[2][r][vs] += la3[r][nt >> 1][2] * a;
                }
    }

    // ===== final: 3-pass c1 reduction (buffer aliases SM_B0) + scatter =====
    float* rb = (float*)(smraw + SM_B0);
#pragma unroll
    for (int t = 0; t < 3; t++) {
        __syncthreads();
#pragma unroll
        for (int r = 0; r < 4; r++)
#pragma unroll
            for (int s = 0; s < 4; s++) {
                int v = (s >> 1) * 8 + qd * 2 + (s & 1);
                rb[er[r] * 68 + v * 4 + wng] = c1[t][r][s];
            }
        __syncthreads();
#pragma unroll
        for (int p = 0; p < 4; p++) {
            int idx = tid + p * 512;
            int e = idx >> 4, v = idx & 15;
            float4 s4 = *(float4*)&rb[e * 68 + v * 4];
            if (e < rows)
                atomicAdd(out + (size_t)s_dst[e] * 64 + 16 + v * 3 + t,
                          (s4.x + s4.y + s4.z + s4.w) * ALPHA);
        }
    }
}

// ---------------------------------------------------------------------------
extern "C" void kernel_launch(void* const* d_in, const int* in_sizes, int n_in,
                              void* d_out, int out_size) {
    const float* x    = (const float*)d_in[0];
    const float* ea   = (const float*)d_in[1];
    const float* el   = (const float*)d_in[2];
    const int*   esrc = (const int*)d_in[3];
    const int*   edst = (const int*)d_in[4];
    const float* W1   = (const float*)d_in[5];
    const float* W2   = (const float*)d_in[6];
    const float* L0   = (const float*)d_in[7];
    const float* L1   = (const float*)d_in[8];
    float* out = (float*)d_out;

    (void)in_sizes; (void)n_in; (void)out_size;

    cudaFuncSetAttribute(k_fused, cudaFuncAttributeMaxDynamicSharedMemorySize, SM_TOTAL);

    // 1) merged prep: self-connection | hidden->A' | W2->B'
    k_prep<<<NB_SC + NB_H + NB_PB, 256>>>(x, el, W1, W2, L0, L1, out);
    // 2) fused GEMM + section-scoped contraction + scatter
    k_fused<<<(E_EDGES + 127) / 128, 512, SM_TOTAL>>>(x, ea, esrc, edst, out);
}

// round 14
// speedup vs baseline: 5.0299x; 1.6718x over previous
#include <cuda_runtime.h>
#include <cuda_fp16.h>
#include <cstdint>

#define N_NODES 25000
#define E_EDGES 200000

// Scratch (__device__ globals — allocation-free rule)
__device__ __half g_A[(size_t)E_EDGES * 64];  // [e][64] fp16 h (scaled 1/8)
__device__ __half g_B[(size_t)1024 * 64];     // [n][64] fp16 W2^T

// ---------------------------------------------------------------------------
// PTX helpers
// ---------------------------------------------------------------------------
__device__ __forceinline__ void mma16816(float* d, const uint32_t* a, const uint32_t* b) {
    asm volatile(
        "mma.sync.aligned.m16n8k16.row.col.f32.f16.f16.f32 "
        "{%0,%1,%2,%3}, {%4,%5,%6,%7}, {%8,%9}, {%0,%1,%2,%3};"
        : "+f"(d[0]), "+f"(d[1]), "+f"(d[2]), "+f"(d[3])
        : "r"(a[0]), "r"(a[1]), "r"(a[2]), "r"(a[3]), "r"(b[0]), "r"(b[1]));
}
__device__ __forceinline__ void ldsm_x4(uint32_t* r, uint32_t addr) {
    asm volatile("ldmatrix.sync.aligned.m8n8.x4.shared.b16 {%0,%1,%2,%3}, [%4];"
                 : "=r"(r[0]), "=r"(r[1]), "=r"(r[2]), "=r"(r[3]) : "r"(addr));
}
__device__ __forceinline__ uint32_t smem_u32(const void* p) {
    uint32_t a;
    asm("{ .reg .u64 t; cvta.to.shared.u64 t, %1; cvt.u32.u64 %0, t; }" : "=r"(a) : "l"(p));
    return a;
}
__device__ __forceinline__ void cpa16(uint32_t dst, const void* src, int src_sz) {
    asm volatile("cp.async.cg.shared.global [%0], [%1], 16, %2;"
                 :: "r"(dst), "l"(src), "r"(src_sz) : "memory");
}
#define CPA_COMMIT() asm volatile("cp.async.commit_group;" ::: "memory")
#define CPA_WAIT0() asm volatile("cp.async.wait_group 0;" ::: "memory")

// ---------------------------------------------------------------------------
// K_prep: merged (self-connection | hidden->A' | W2->B') via blockIdx dispatch
// ---------------------------------------------------------------------------
#define NB_SC 6250
#define NB_H 782
#define NB_PB 256

__global__ void __launch_bounds__(256) k_prep(
    const float* __restrict__ x, const float* __restrict__ el,
    const float* __restrict__ W1, const float* __restrict__ W2,
    const float* __restrict__ L0, const float* __restrict__ L1,
    float* __restrict__ out) {
    __shared__ float sA[512];
    int b = blockIdx.x, t = threadIdx.x;
    if (b < NB_SC) {
        sA[t] = L0[t];
        sA[256 + t] = L1[t];
        __syncthreads();
        int idx = b * 256 + t;
        int n = idx >> 6, o = idx & 63;
        const float* xr = x + (size_t)n * 64;
        float acc = 0.f;
        if (o < 16) {
            int v = o;
#pragma unroll
            for (int u = 0; u < 16; u++) acc += xr[u] * sA[u * 16 + v];
        } else {
            int q = o - 16;
            int v = q / 3, k = q - v * 3;
#pragma unroll
            for (int u = 0; u < 16; u++) acc += xr[16 + u * 3 + k] * sA[256 + u * 16 + v];
        }
        out[idx] = acc * 0.25f;
    } else if (b < NB_SC + NB_H) {
        sA[t] = W1[t];
        sA[t + 256] = W1[t + 256];
        __syncthreads();
        int e = (b - NB_SC) * 256 + t;
        if (e >= E_EDGES) return;
        float L = el[e];
        float r[8];
#pragma unroll
        for (int i = 0; i < 8; i++) {
            float d = L - (5.0f / 7.0f) * (float)i;
            r[i] = __expf(-0.5f * d * d);
        }
        uint32_t hiP[32];
#pragma unroll 4
        for (int c2 = 0; c2 < 32; c2++) {
            float z0 = 0.f, z1 = 0.f;
#pragma unroll
            for (int i = 0; i < 8; i++) {
                z0 += r[i] * sA[i * 64 + 2 * c2];
                z1 += r[i] * sA[i * 64 + 2 * c2 + 1];
            }
            z0 *= 0.35355339059327373f;
            z1 *= 0.35355339059327373f;
            float h0 = z0 / (1.f + __expf(-z0)) * 0.125f;  // silu * (1/8)
            float h1 = z1 / (1.f + __expf(-z1)) * 0.125f;
            __half b0 = __float2half_rn(h0);
            __half b1 = __float2half_rn(h1);
            hiP[c2] = ((uint32_t)__half_as_ushort(b1) << 16) | __half_as_ushort(b0);
        }
        uint4* row = (uint4*)(g_A + (size_t)e * 64);
        const uint4* hp = (const uint4*)hiP;
#pragma unroll
        for (int i = 0; i < 8; i++) row[i] = hp[i];
    } else {
        int idx = (b - NB_SC - NB_H) * 256 + t;  // < 65536
        int n = idx >> 6, k = idx & 63;
        g_B[(size_t)n * 64 + k] = __float2half_rn(W2[k * 1024 + n]);
    }
}

// ---------------------------------------------------------------------------
// K_fused: 128-edge tile, 512 threads. Single-pass fp16 GEMM (K=64) +
// fragment-side contraction with section-scoped register partials.
// ---------------------------------------------------------------------------
#define SAB_PITCH 72  // fp16/row (144B rows, ldmatrix conflict-free)
#define SXP 68        // s_x pitch in floats
#define SM_A 0
#define SM_B0 18432
#define SM_B1 36864
#define SM_X 55296
#define SM_EA 90112
#define SM_DST 92160
#define SM_L0 92672
#define SM_L1 101376
#define SM_TOTAL 110080
// po0 flush buffer aliases SM_L0 (l0+l1, 17408 B, dead after h=3)
// c1 reduction buffer aliases SM_B0 (B0+B1, 36864 B >= 34816, dead after h=7)

__global__ void __launch_bounds__(512, 1)
k_fused(const float* __restrict__ x,
        const float* __restrict__ ea,
        const int* __restrict__ esrc,
        const int* __restrict__ edst,
        float* __restrict__ out) {
    extern __shared__ char smraw[];
    uint32_t sbase = smem_u32(smraw);
    float* s_x = (float*)(smraw + SM_X);
    float* s_ea = (float*)(smraw + SM_EA);
    int* s_dst = (int*)(smraw + SM_DST);
    float* s_l0 = (float*)(smraw + SM_L0);
    float* s_l1 = (float*)(smraw + SM_L1);

    int tid = threadIdx.x;
    long e0 = (long)blockIdx.x * 128;
    int rows = (int)(E_EDGES - e0);
    if (rows > 128) rows = 128;

    // ---- stage group 0: A tile, x gather, ea, dst, B(0)
    for (int f = tid; f < 128 * 8; f += 512) {
        int r = f >> 3, q = f & 7;
        int ok = (r < rows) ? 16 : 0;
        cpa16(sbase + SM_A + r * (SAB_PITCH * 2) + q * 16,
              (const char*)(g_A + (size_t)(e0 + (ok ? r : 0)) * 64) + q * 16, ok);
    }
    for (int f = tid; f < 128 * 16; f += 512) {
        int r = f >> 4, q = f & 15;
        int ok = (r < rows) ? 16 : 0;
        int sn = ok ? esrc[e0 + r] : 0;
        cpa16(sbase + SM_X + r * (SXP * 4) + q * 16,
              (const char*)(x + (size_t)sn * 64) + q * 16, ok);
    }
    if (tid < 128) {
        int ok = (tid < rows) ? 16 : 0;
        cpa16(sbase + SM_EA + tid * 16,
              (const char*)(ea + (size_t)(e0 + (ok ? tid : 0)) * 4), ok);
    }
    if (tid < 32) {
        int ok = (tid * 4 < rows) ? 16 : 0;
        cpa16(sbase + SM_DST + tid * 16,
              (const char*)(edst + e0 + (ok ? tid * 4 : 0)), ok);
    }
    for (int f = tid; f < 128 * 8; f += 512) {
        int r = f >> 3, q = f & 7;
        cpa16(sbase + SM_B0 + r * (SAB_PITCH * 2) + q * 16,
              (const char*)(g_B + (size_t)r * 64) + q * 16, 16);
    }
    CPA_COMMIT();

    // warp roles (16 warps, 4x4 grid of 32x32 tiles over 128x128)
    int wid = tid >> 5, lane = tid & 31;
    int wm = (wid >> 2) * 32;
    int wn = (wid & 3) * 32;
    int wng = wid & 3;
    int grp = lane >> 2, qd = lane & 3;

    // ldmatrix lane bases
    int selA = lane >> 3;
    int rA = wm + ((selA & 1) << 3) + (lane & 7);
    int cA = (selA >> 1) << 3;
    uint32_t aF = sbase + SM_A + (uint32_t)(rA * SAB_PITCH + cA) * 2;
    int rB4 = wn + ((lane >> 4) << 3) + (lane & 7);
    int cB4 = ((lane >> 3) & 1) << 3;
    uint32_t bOff = (uint32_t)(rB4 * SAB_PITCH + cB4) * 2;

    // fragment row coordinates
    int er[4];
#pragma unroll
    for (int r = 0; r < 4; r++) er[r] = wm + ((r >> 1) << 4) + ((r & 1) << 3) + grp;

    const float ALPHA = 0.17677669529663689f;  // 1/sqrt(32)

    // shared GEMM body for one half (single fp16 term, K=64)
    auto gemm_half = [&](int h, float (&acc)[2][4][4]) {
        uint32_t bufo = (h & 1) ? SM_B1 : SM_B0;
        CPA_WAIT0();
        __syncthreads();  // B(h) (+ group0 on h=0) ready; prev phase done
        if (h == 0) {
            // precompute l0 = xj0*sh0, l1 = (x1 . sh1)/sqrt(3)
            for (int f = tid; f < 2048; f += 512) {
                int e = f >> 4, u = f & 15;
                const float* xr = s_x + e * SXP;
                s_l0[e * 17 + u] = xr[u] * s_ea[e * 4 + 0];
                const float* x1 = xr + 16 + u * 3;
                s_l1[e * 17 + u] = 0.57735026918962576f *
                                   (x1[0] * s_ea[e * 4 + 1] + x1[1] * s_ea[e * 4 + 2] +
                                    x1[2] * s_ea[e * 4 + 3]);
            }
            __syncthreads();
        }
        // prefetch B(h+1)
        if (h < 7) {
            uint32_t dstb = ((h & 1) ? SM_B0 : SM_B1) + sbase;
            const __half* srcb = g_B + (size_t)(h + 1) * 128 * 64;
            for (int f = tid; f < 128 * 8; f += 512) {
                int r = f >> 3, q = f & 7;
                cpa16(dstb + r * (SAB_PITCH * 2) + q * 16,
                      (const char*)(srcb + (size_t)r * 64) + q * 16, 16);
            }
            CPA_COMMIT();
        }
#pragma unroll
        for (int mt = 0; mt < 2; mt++)
#pragma unroll
            for (int nt = 0; nt < 4; nt++)
#pragma unroll
                for (int j = 0; j < 4; j++) acc[mt][nt][j] = 0.f;
        uint32_t bF = sbase + bufo + bOff;
#pragma unroll
        for (int kt = 0; kt < 4; kt++) {
            int kc = kt * 16;
            uint32_t ah[2][4], bb[2][4];
#pragma unroll
            for (int mt = 0; mt < 2; mt++)
                ldsm_x4(ah[mt], aF + (uint32_t)(mt * 16 * SAB_PITCH + kc) * 2);
#pragma unroll
            for (int p = 0; p < 2; p++)
                ldsm_x4(bb[p], bF + (uint32_t)(p * 16 * SAB_PITCH + kc) * 2);
#pragma unroll
            for (int mt = 0; mt < 2; mt++)
#pragma unroll
                for (int nt = 0; nt < 4; nt++)
                    mma16816(acc[mt][nt], ah[mt], &bb[nt >> 1][(nt & 1) * 2]);
        }
    };

    // ================= sections 0,1 (h=0..3): po0 only =================
    {
        float po0[4][4] = {};
#pragma unroll 1
        for (int h = 0; h < 4; h++) {
            float acc[2][4][4];
            gemm_half(h, acc);
            int u0 = (h & 1) * 8 + (wn >> 4);
            const float* lt = (h < 2) ? s_l0 : s_l1;
            float la[4][2];
#pragma unroll
            for (int r = 0; r < 4; r++) {
                la[r][0] = lt[er[r] * 17 + u0];
                la[r][1] = lt[er[r] * 17 + u0 + 1];
            }
#pragma unroll
            for (int mt = 0; mt < 2; mt++)
#pragma unroll
                for (int nt = 0; nt < 4; nt++)
#pragma unroll
                    for (int j = 0; j < 4; j++)
                        po0[mt * 2 + (j >> 1)][(nt & 1) * 2 + (j & 1)] +=
                            la[mt * 2 + (j >> 1)][nt >> 1] * acc[mt][nt][j];
        }
        // flush po0 (reduce across 4 wn-groups) + scatter o0 outputs.
        float* fb = (float*)(smraw + SM_L0);
#pragma unroll 1
        for (int sp = 0; sp < 2; sp++) {
            __syncthreads();
            if ((wm >> 6) == sp) {
#pragma unroll
                for (int r = 0; r < 4; r++)
#pragma unroll
                    for (int s = 0; s < 4; s++) {
                        int v = (s >> 1) * 8 + qd * 2 + (s & 1);
                        fb[(er[r] - sp * 64) * 68 + v * 4 + wng] = po0[r][s];
                    }
            }
            __syncthreads();
#pragma unroll
            for (int p = 0; p < 2; p++) {
                int idx = tid + p * 512;
                int e2 = idx >> 4, v = idx & 15;
                int e = sp * 64 + e2;
                float4 s4 = *(float4*)&fb[e2 * 68 + v * 4];
                if (e < rows)
                    atomicAdd(out + (size_t)s_dst[e] * 64 + v,
                              (s4.x + s4.y + s4.z + s4.w) * ALPHA);
            }
        }
    }

    // ================= section 2 (h=4,5): ps2 -> c1 seed =================
    float c1[3][4][4];
    {
        float ps2[4][4] = {};
#pragma unroll 1
        for (int h = 4; h < 6; h++) {
            float acc[2][4][4];
            gemm_half(h, acc);
            int u0 = (h & 1) * 8 + (wn >> 4);
            float la[4][2];
#pragma unroll
            for (int r = 0; r < 4; r++) {
                la[r][0] = s_x[er[r] * SXP + u0];
                la[r][1] = s_x[er[r] * SXP + u0 + 1];
            }
#pragma unroll
            for (int mt = 0; mt < 2; mt++)
#pragma unroll
                for (int nt = 0; nt < 4; nt++)
#pragma unroll
                    for (int j = 0; j < 4; j++)
                        ps2[mt * 2 + (j >> 1)][(nt & 1) * 2 + (j & 1)] +=
                            la[mt * 2 + (j >> 1)][nt >> 1] * acc[mt][nt][j];
        }
#pragma unroll
        for (int r = 0; r < 4; r++) {
            float h1 = s_ea[er[r] * 4 + 1];
            float h2 = s_ea[er[r] * 4 + 2];
            float h3 = s_ea[er[r] * 4 + 3];
#pragma unroll
            for (int s = 0; s < 4; s++) {
                c1[0][r][s] = ps2[r][s] * h1;
                c1[1][r][s] = ps2[r][s] * h2;
                c1[2][r][s] = ps2[r][s] * h3;
            }
        }
    }

    // ========== section 3 (h=6,7): accumulate into c1 (sh0 folded) ==========
#pragma unroll 1
    for (int h = 6; h < 8; h++) {
        float acc[2][4][4];
        gemm_half(h, acc);
        int u0 = (h & 1) * 8 + (wn >> 4);
        float la3[4][2][3];
#pragma unroll
        for (int r = 0; r < 4; r++) {
            float sh0 = s_ea[er[r] * 4 + 0];
#pragma unroll
            for (int u = 0; u < 2; u++) {
                const float* x1 = s_x + er[r] * SXP + 16 + (u0 + u) * 3;
                la3[r][u][0] = x1[0] * sh0;
                la3[r][u][1] = x1[1] * sh0;
                la3[r][u][2] = x1[2] * sh0;
            }
        }
#pragma unroll
        for (int mt = 0; mt < 2; mt++)
#pragma unroll
            for (int nt = 0; nt < 4; nt++)
#pragma unroll
                for (int j = 0; j < 4; j++) {
                    int r = mt * 2 + (j >> 1), vs = (nt & 1) * 2 + (j & 1);
                    float a = acc[mt][nt][j];
                    c1[0][r][vs] += la3[r][nt >> 1][0] * a;
                    c1[1][r][vs] += la3[r][nt >> 1][1] * a;
                    c1[2][r][vs] += la3[r][nt >> 1][2] * a;
                }
    }

    // ===== final: 3-pass c1 reduction (buffer aliases SM_B0) + scatter =====
    float* rb = (float*)(smraw + SM_B0);
#pragma unroll
    for (int t = 0; t < 3; t++) {
        __syncthreads();
#pragma unroll
        for (int r = 0; r < 4; r++)
#pragma unroll
            for (int s = 0; s < 4; s++) {
                int v = (s >> 1) * 8 + qd * 2 + (s & 1);
                rb[er[r] * 68 + v * 4 + wng] = c1[t][r][s];
            }
        __syncthreads();
#pragma unroll
        for (int p = 0; p < 4; p++) {
            int idx = tid + p * 512;
            int e = idx >> 4, v = idx & 15;
            float4 s4 = *(float4*)&rb[e * 68 + v * 4];
            if (e < rows)
                atomicAdd(out + (size_t)s_dst[e] * 64 + 16 + v * 3 + t,
                          (s4.x + s4.y + s4.z + s4.w) * ALPHA);
        }
    }
}

// ---------------------------------------------------------------------------
extern "C" void kernel_launch(void* const* d_in, const int* in_sizes, int n_in,
                              void* d_out, int out_size) {
    const float* x    = (const float*)d_in[0];
    const float* ea   = (const float*)d_in[1];
    const float* el   = (const float*)d_in[2];
    const int*   esrc = (const int*)d_in[3];
    const int*   edst = (const int*)d_in[4];
    const float* W1   = (const float*)d_in[5];
    const float* W2   = (const float*)d_in[6];
    const float* L0   = (const float*)d_in[7];
    const float* L1   = (const float*)d_in[8];
    float* out = (float*)d_out;

    (void)in_sizes; (void)n_in; (void)out_size;

    cudaFuncSetAttribute(k_fused, cudaFuncAttributeMaxDynamicSharedMemorySize, SM_TOTAL);

    // 1) merged prep: self-connection | hidden->A (fp16) | W2->B (fp16)
    k_prep<<<NB_SC + NB_H + NB_PB, 256>>>(x, el, W1, W2, L0, L1, out);
    // 2) fused fp16 GEMM + section-scoped contraction + scatter
    k_fused<<<(E_EDGES + 127) / 128, 512, SM_TOTAL>>>(x, ea, esrc, edst, out);
}

// round 16
// speedup vs baseline: 5.0950x; 1.0130x over previous
#include <cuda_runtime.h>
#include <cuda_fp16.h>
#include <cstdint>

#define N_NODES 25000
#define E_EDGES 200000

// Scratch (__device__ globals — allocation-free rule)
__device__ __half g_A[(size_t)E_EDGES * 64];  // [e][64] fp16 h (scaled 1/8)
__device__ __half g_B[(size_t)1024 * 64];     // [n][64] fp16 W2^T

// ---------------------------------------------------------------------------
// PTX helpers
// ---------------------------------------------------------------------------
__device__ __forceinline__ void mma16816(float* d, const uint32_t* a, const uint32_t* b) {
    asm volatile(
        "mma.sync.aligned.m16n8k16.row.col.f32.f16.f16.f32 "
        "{%0,%1,%2,%3}, {%4,%5,%6,%7}, {%8,%9}, {%0,%1,%2,%3};"
        : "+f"(d[0]), "+f"(d[1]), "+f"(d[2]), "+f"(d[3])
        : "r"(a[0]), "r"(a[1]), "r"(a[2]), "r"(a[3]), "r"(b[0]), "r"(b[1]));
}
__device__ __forceinline__ void ldsm_x4(uint32_t* r, uint32_t addr) {
    asm volatile("ldmatrix.sync.aligned.m8n8.x4.shared.b16 {%0,%1,%2,%3}, [%4];"
                 : "=r"(r[0]), "=r"(r[1]), "=r"(r[2]), "=r"(r[3]) : "r"(addr));
}
__device__ __forceinline__ uint32_t smem_u32(const void* p) {
    uint32_t a;
    asm("{ .reg .u64 t; cvta.to.shared.u64 t, %1; cvt.u32.u64 %0, t; }" : "=r"(a) : "l"(p));
    return a;
}
__device__ __forceinline__ void cpa16(uint32_t dst, const void* src, int src_sz) {
    asm volatile("cp.async.cg.shared.global [%0], [%1], 16, %2;"
                 :: "r"(dst), "l"(src), "r"(src_sz) : "memory");
}
#define CPA_COMMIT() asm volatile("cp.async.commit_group;" ::: "memory")
#define CPA_WAIT0() asm volatile("cp.async.wait_group 0;" ::: "memory")

// ---------------------------------------------------------------------------
// K_prep: merged (self-connection | hidden->A' | W2->B') via blockIdx dispatch
// ---------------------------------------------------------------------------
#define NB_SC 6250
#define NB_H 782
#define NB_PB 256

__global__ void __launch_bounds__(256) k_prep(
    const float* __restrict__ x, const float* __restrict__ el,
    const float* __restrict__ W1, const float* __restrict__ W2,
    const float* __restrict__ L0, const float* __restrict__ L1,
    float* __restrict__ out) {
    __shared__ float sA[512];
    int b = blockIdx.x, t = threadIdx.x;
    if (b < NB_SC) {
        sA[t] = L0[t];
        sA[256 + t] = L1[t];
        __syncthreads();
        int idx = b * 256 + t;
        int n = idx >> 6, o = idx & 63;
        const float* xr = x + (size_t)n * 64;
        float acc = 0.f;
        if (o < 16) {
            int v = o;
#pragma unroll
            for (int u = 0; u < 16; u++) acc += xr[u] * sA[u * 16 + v];
        } else {
            int q = o - 16;
            int v = q / 3, k = q - v * 3;
#pragma unroll
            for (int u = 0; u < 16; u++) acc += xr[16 + u * 3 + k] * sA[256 + u * 16 + v];
        }
        out[idx] = acc * 0.25f;
    } else if (b < NB_SC + NB_H) {
        sA[t] = W1[t];
        sA[t + 256] = W1[t + 256];
        __syncthreads();
        int e = (b - NB_SC) * 256 + t;
        if (e >= E_EDGES) return;
        float L = el[e];
        float r[8];
#pragma unroll
        for (int i = 0; i < 8; i++) {
            float d = L - (5.0f / 7.0f) * (float)i;
            r[i] = __expf(-0.5f * d * d);
        }
        uint32_t hiP[32];
#pragma unroll 4
        for (int c2 = 0; c2 < 32; c2++) {
            float z0 = 0.f, z1 = 0.f;
#pragma unroll
            for (int i = 0; i < 8; i++) {
                z0 += r[i] * sA[i * 64 + 2 * c2];
                z1 += r[i] * sA[i * 64 + 2 * c2 + 1];
            }
            z0 *= 0.35355339059327373f;
            z1 *= 0.35355339059327373f;
            float h0 = z0 / (1.f + __expf(-z0)) * 0.125f;  // silu * (1/8)
            float h1 = z1 / (1.f + __expf(-z1)) * 0.125f;
            __half b0 = __float2half_rn(h0);
            __half b1 = __float2half_rn(h1);
            hiP[c2] = ((uint32_t)__half_as_ushort(b1) << 16) | __half_as_ushort(b0);
        }
        uint4* row = (uint4*)(g_A + (size_t)e * 64);
        const uint4* hp = (const uint4*)hiP;
#pragma unroll
        for (int i = 0; i < 8; i++) row[i] = hp[i];
    } else {
        int idx = (b - NB_SC - NB_H) * 256 + t;  // < 65536
        int n = idx >> 6, k = idx & 63;
        g_B[(size_t)n * 64 + k] = __float2half_rn(W2[k * 1024 + n]);
    }
}

// ---------------------------------------------------------------------------
// K_fused: 128-edge tile, 512 threads. B FULLY smem-resident (144 KB) ->
// zero barriers / zero async-waits in the 8-half GEMM+contraction mainloop.
// ---------------------------------------------------------------------------
#define SAB_PITCH 72  // fp16/row (144B rows, ldmatrix conflict-free)
#define SXP 68        // s_x pitch in floats
#define SM_A 0
#define SM_B 18432
#define SM_X 165888
#define SM_EA 200704
#define SM_DST 202752
#define SM_L0 203264
#define SM_L1 211968
#define SM_TOTAL 220672
// po0 flush buffer aliases SM_L0 (l0+l1, 17408 B, dead after section 1)
// c1 reduction buffer aliases SM_B (dead after the pre-reduction barrier)

__global__ void __launch_bounds__(512, 1)
k_fused(const float* __restrict__ x,
        const float* __restrict__ ea,
        const int* __restrict__ esrc,
        const int* __restrict__ edst,
        float* __restrict__ out) {
    extern __shared__ char smraw[];
    uint32_t sbase = smem_u32(smraw);
    float* s_x = (float*)(smraw + SM_X);
    float* s_ea = (float*)(smraw + SM_EA);
    int* s_dst = (int*)(smraw + SM_DST);
    float* s_l0 = (float*)(smraw + SM_L0);
    float* s_l1 = (float*)(smraw + SM_L1);

    int tid = threadIdx.x;
    long e0 = (long)blockIdx.x * 128;
    int rows = (int)(E_EDGES - e0);
    if (rows > 128) rows = 128;

    // ---- stage everything once: A tile, full B, x gather, ea, dst
    for (int f = tid; f < 128 * 8; f += 512) {
        int r = f >> 3, q = f & 7;
        int ok = (r < rows) ? 16 : 0;
        cpa16(sbase + SM_A + r * (SAB_PITCH * 2) + q * 16,
              (const char*)(g_A + (size_t)(e0 + (ok ? r : 0)) * 64) + q * 16, ok);
    }
    for (int f = tid; f < 1024 * 8; f += 512) {
        int r = f >> 3, q = f & 7;
        cpa16(sbase + SM_B + r * (SAB_PITCH * 2) + q * 16,
              (const char*)(g_B + (size_t)r * 64) + q * 16, 16);
    }
    for (int f = tid; f < 128 * 16; f += 512) {
        int r = f >> 4, q = f & 15;
        int ok = (r < rows) ? 16 : 0;
        int sn = ok ? esrc[e0 + r] : 0;
        cpa16(sbase + SM_X + r * (SXP * 4) + q * 16,
              (const char*)(x + (size_t)sn * 64) + q * 16, ok);
    }
    if (tid < 128) {
        int ok = (tid < rows) ? 16 : 0;
        cpa16(sbase + SM_EA + tid * 16,
              (const char*)(ea + (size_t)(e0 + (ok ? tid : 0)) * 4), ok);
    }
    if (tid < 32) {
        int ok = (tid * 4 < rows) ? 16 : 0;
        cpa16(sbase + SM_DST + tid * 16,
              (const char*)(edst + e0 + (ok ? tid * 4 : 0)), ok);
    }
    CPA_COMMIT();

    // warp roles (16 warps, 4x4 grid of 32x32 tiles over 128x128)
    int wid = tid >> 5, lane = tid & 31;
    int wm = (wid >> 2) * 32;
    int wn = (wid & 3) * 32;
    int wng = wid & 3;
    int grp = lane >> 2, qd = lane & 3;

    // ldmatrix lane bases
    int selA = lane >> 3;
    int rA = wm + ((selA & 1) << 3) + (lane & 7);
    int cA = (selA >> 1) << 3;
    uint32_t aF = sbase + SM_A + (uint32_t)(rA * SAB_PITCH + cA) * 2;
    int rB4 = wn + ((lane >> 4) << 3) + (lane & 7);
    int cB4 = ((lane >> 3) & 1) << 3;
    uint32_t bF0 = sbase + SM_B + (uint32_t)(rB4 * SAB_PITCH + cB4) * 2;

    // fragment row coordinates
    int er[4];
#pragma unroll
    for (int r = 0; r < 4; r++) er[r] = wm + ((r >> 1) << 4) + ((r & 1) << 3) + grp;

    const float ALPHA = 0.17677669529663689f;  // 1/sqrt(32)

    // ---- single wait + barrier, then precompute l0/l1, then free-run
    CPA_WAIT0();
    __syncthreads();
    for (int f = tid; f < 2048; f += 512) {
        int e = f >> 4, u = f & 15;
        const float* xr = s_x + e * SXP;
        s_l0[e * 17 + u] = xr[u] * s_ea[e * 4 + 0];
        const float* x1 = xr + 16 + u * 3;
        s_l1[e * 17 + u] = 0.57735026918962576f *
                           (x1[0] * s_ea[e * 4 + 1] + x1[1] * s_ea[e * 4 + 2] +
                            x1[2] * s_ea[e * 4 + 3]);
    }
    __syncthreads();

    // GEMM body for one half (fp16, K=64). No syncs, no waits.
    auto gemm_half = [&](int h, float (&acc)[2][4][4]) {
#pragma unroll
        for (int mt = 0; mt < 2; mt++)
#pragma unroll
            for (int nt = 0; nt < 4; nt++)
#pragma unroll
                for (int j = 0; j < 4; j++) acc[mt][nt][j] = 0.f;
        uint32_t bF = bF0 + (uint32_t)h * (128 * SAB_PITCH * 2);
#pragma unroll
        for (int kt = 0; kt < 4; kt++) {
            int kc = kt * 16;
            uint32_t ah[2][4], bb[2][4];
#pragma unroll
            for (int mt = 0; mt < 2; mt++)
                ldsm_x4(ah[mt], aF + (uint32_t)(mt * 16 * SAB_PITCH + kc) * 2);
#pragma unroll
            for (int p = 0; p < 2; p++)
                ldsm_x4(bb[p], bF + (uint32_t)(p * 16 * SAB_PITCH + kc) * 2);
#pragma unroll
            for (int mt = 0; mt < 2; mt++)
#pragma unroll
                for (int nt = 0; nt < 4; nt++)
                    mma16816(acc[mt][nt], ah[mt], &bb[nt >> 1][(nt & 1) * 2]);
        }
    };

    // ================= sections 0,1 (h=0..3): po0 only =================
    {
        float po0[4][4] = {};
#pragma unroll 1
        for (int h = 0; h < 4; h++) {
            float acc[2][4][4];
            gemm_half(h, acc);
            int u0 = (h & 1) * 8 + (wn >> 4);
            const float* lt = (h < 2) ? s_l0 : s_l1;
            float la[4][2];
#pragma unroll
            for (int r = 0; r < 4; r++) {
                la[r][0] = lt[er[r] * 17 + u0];
                la[r][1] = lt[er[r] * 17 + u0 + 1];
            }
#pragma unroll
            for (int mt = 0; mt < 2; mt++)
#pragma unroll
                for (int nt = 0; nt < 4; nt++)
#pragma unroll
                    for (int j = 0; j < 4; j++)
                        po0[mt * 2 + (j >> 1)][(nt & 1) * 2 + (j & 1)] +=
                            la[mt * 2 + (j >> 1)][nt >> 1] * acc[mt][nt][j];
        }
        // flush po0 (reduce across 4 wn-groups) + scatter o0 outputs.
        // Buffer aliases l0/l1 (dead after section 1): [64][68] x 2 sub-passes.
        float* fb = (float*)(smraw + SM_L0);
#pragma unroll 1
        for (int sp = 0; sp < 2; sp++) {
            __syncthreads();
            if ((wm >> 6) == sp) {
#pragma unroll
                for (int r = 0; r < 4; r++)
#pragma unroll
                    for (int s = 0; s < 4; s++) {
                        int v = (s >> 1) * 8 + qd * 2 + (s & 1);
                        fb[(er[r] - sp * 64) * 68 + v * 4 + wng] = po0[r][s];
                    }
            }
            __syncthreads();
#pragma unroll
            for (int p = 0; p < 2; p++) {
                int idx = tid + p * 512;
                int e2 = idx >> 4, v = idx & 15;
                int e = sp * 64 + e2;
                float4 s4 = *(float4*)&fb[e2 * 68 + v * 4];
                if (e < rows)
                    atomicAdd(out + (size_t)s_dst[e] * 64 + v,
                              (s4.x + s4.y + s4.z + s4.w) * ALPHA);
            }
        }
    }

    // ================= section 2 (h=4,5): ps2 -> c1 seed =================
    float c1[3][4][4];
    {
        float ps2[4][4] = {};
#pragma unroll 1
        for (int h = 4; h < 6; h++) {
            float acc[2][4][4];
            gemm_half(h, acc);
            int u0 = (h & 1) * 8 + (wn >> 4);
            float la[4][2];
#pragma unroll
            for (int r = 0; r < 4; r++) {
                la[r][0] = s_x[er[r] * SXP + u0];
                la[r][1] = s_x[er[r] * SXP + u0 + 1];
            }
#pragma unroll
            for (int mt = 0; mt < 2; mt++)
#pragma unroll
                for (int nt = 0; nt < 4; nt++)
#pragma unroll
                    for (int j = 0; j < 4; j++)
                        ps2[mt * 2 + (j >> 1)][(nt & 1) * 2 + (j & 1)] +=
                            la[mt * 2 + (j >> 1)][nt >> 1] * acc[mt][nt][j];
        }
#pragma unroll
        for (int r = 0; r < 4; r++) {
            float h1 = s_ea[er[r] * 4 + 1];
            float h2 = s_ea[er[r] * 4 + 2];
            float h3 = s_ea[er[r] * 4 + 3];
#pragma unroll
            for (int s = 0; s < 4; s++) {
                c1[0][r][s] = ps2[r][s] * h1;
                c1[1][r][s] = ps2[r][s] * h2;
                c1[2][r][s] = ps2[r][s] * h3;
            }
        }
    }

    // ========== section 3 (h=6,7): accumulate into c1 (sh0 folded) ==========
#pragma unroll 1
    for (int h = 6; h < 8; h++) {
        float acc[2][4][4];
        gemm_half(h, acc);
        int u0 = (h & 1) * 8 + (wn >> 4);
        float la3[4][2][3];
#pragma unroll
        for (int r = 0; r < 4; r++) {
            float sh0 = s_ea[er[r] * 4 + 0];
#pragma unroll
            for (int u = 0; u < 2; u++) {
                const float* x1 = s_x + er[r] * SXP + 16 + (u0 + u) * 3;
                la3[r][u][0] = x1[0] * sh0;
                la3[r][u][1] = x1[1] * sh0;
                la3[r][u][2] = x1[2] * sh0;
            }
        }
#pragma unroll
        for (int mt = 0; mt < 2; mt++)
#pragma unroll
            for (int nt = 0; nt < 4; nt++)
#pragma unroll
                for (int j = 0; j < 4; j++) {
                    int r = mt * 2 + (j >> 1), vs = (nt & 1) * 2 + (j & 1);
                    float a = acc[mt][nt][j];
                    c1[0][r][vs] += la3[r][nt >> 1][0] * a;
                    c1[1][r][vs] += la3[r][nt >> 1][1] * a;
                    c1[2][r][vs] += la3[r][nt >> 1][2] * a;
                }
    }

    // ===== final: 3-pass c1 reduction (buffer aliases SM_B) + scatter =====
    float* rb = (float*)(smraw + SM_B);
#pragma unroll
    for (int t = 0; t < 3; t++) {
        __syncthreads();
#pragma unroll
        for (int r = 0; r < 4; r++)
#pragma unroll
            for (int s = 0; s < 4; s++) {
                int v = (s >> 1) * 8 + qd * 2 + (s & 1);
                rb[er[r] * 68 + v * 4 + wng] = c1[t][r][s];
            }
        __syncthreads();
#pragma unroll
        for (int p = 0; p < 4; p++) {
            int idx = tid + p * 512;
            int e = idx >> 4, v = idx & 15;
            float4 s4 = *(float4*)&rb[e * 68 + v * 4];
            if (e < rows)
                atomicAdd(out + (size_t)s_dst[e] * 64 + 16 + v * 3 + t,
                          (s4.x + s4.y + s4.z + s4.w) * ALPHA);
        }
    }
}

// ---------------------------------------------------------------------------
extern "C" void kernel_launch(void* const* d_in, const int* in_sizes, int n_in,
                              void* d_out, int out_size) {
    const float* x    = (const float*)d_in[0];
    const float* ea   = (const float*)d_in[1];
    const float* el   = (const float*)d_in[2];
    const int*   esrc = (const int*)d_in[3];
    const int*   edst = (const int*)d_in[4];
    const float* W1   = (const float*)d_in[5];
    const float* W2   = (const float*)d_in[6];
    const float* L0   = (const float*)d_in[7];
    const float* L1   = (const float*)d_in[8];
    float* out = (float*)d_out;

    (void)in_sizes; (void)n_in; (void)out_size;

    cudaFuncSetAttribute(k_fused, cudaFuncAttributeMaxDynamicSharedMemorySize, SM_TOTAL);

    // 1) merged prep: self-connection | hidden->A (fp16) | W2->B (fp16)
    k_prep<<<NB_SC + NB_H + NB_PB, 256>>>(x, el, W1, W2, L0, L1, out);
    // 2) fused fp16 GEMM (B resident, barrier-free mainloop) + scatter
    k_fused<<<(E_EDGES + 127) / 128, 512, SM_TOTAL>>>(x, ea, esrc, edst, out);
}